// round 2
// baseline (speedup 1.0000x reference)
#include <cuda_runtime.h>

// SPU transformer bound propagation — pure elementwise streaming kernel.
// R2: 2 float4 chunks per thread per array (MLP=8 front-batched LDG.128),
// streaming cache hints (__ldcs/__stcs) since working set (320MB) >> L2 (126MB)
// with zero reuse.

__device__ __forceinline__ float spu_f(float x) {
    if (x >= 0.0f) {
        return fmaf(x, x, -0.5f);
    } else {
        return __fdividef(1.0f, 1.0f + __expf(x)) - 1.0f;
    }
}

struct Pair { float lo, hi; };

__device__ __forceinline__ Pair spu_row(
    float l, float u,
    float p1l, float p1u,
    float q1l, float q1u,
    float b0l, float b0u)
{
    float sl = spu_f(l);
    float su = spu_f(u);

    bool neg   = (u <= 0.0f);
    bool pos   = (l >= 0.0f);
    bool cross = !(neg || pos);

    float all_slopes = (su - sl) / (u - l);

    float s0 = neg ? all_slopes : 0.0f;
    float s1 = neg ? 0.0f : all_slopes;

    bool neg_slope = (all_slopes < 0.0f);
    float lo = neg_slope ? su : sl;
    float hi = neg_slope ? sl : su;
    if (cross) lo = -0.5f;

    float sh1 = fmaf(-s1, u, su);
    float sh0 = fmaf(-s0, l, sl);
    if (cross) sh0 = -0.5f;
    if (neg)   sh1 = sl;

    float s1p = fmaxf(s1, 0.0f), s1n = fminf(s1, 0.0f);
    float s0p = fmaxf(s0, 0.0f), s0n = fminf(s0, 0.0f);

    float UBM = fmaf(s1p, p1u, s1n * p1l);
    float UBV = fmaf(s1p, q1u, fmaf(s1n, q1l, sh1));
    float LBM = fmaf(s0p, p1l, s0n * p1u);
    float LBV = fmaf(s0n, q1l, fmaf(s0p, q1u, sh0));

    float lower = fmaf(fmaxf(LBM, 0.0f), b0l, fmaf(fminf(LBM, 0.0f), b0u, LBV));
    float upper = fmaf(fmaxf(UBM, 0.0f), b0u, fmaf(fminf(UBM, 0.0f), b0l, UBV));

    if (lower > lo) lo = lower;
    if (upper < hi) hi = upper;

    Pair r; r.lo = lo; r.hi = hi;
    return r;
}

__device__ __forceinline__ float4 process_chunk(float4 b, float4 sp, float4 sh, float4 bp) {
    Pair r0 = spu_row(b.x, b.y, sp.x, sp.y, sh.x, sh.y, bp.x, bp.y);
    Pair r1 = spu_row(b.z, b.w, sp.z, sp.w, sh.z, sh.w, bp.z, bp.w);
    float4 o;
    o.x = r0.lo; o.y = r0.hi;
    o.z = r1.lo; o.w = r1.hi;
    return o;
}

__global__ __launch_bounds__(256) void spu_transformer_kernel(
    const float4* __restrict__ bounds,
    const float4* __restrict__ slopes_prev,
    const float4* __restrict__ shifts_prev,
    const float4* __restrict__ bounds_prev,
    float4* __restrict__ out,
    int n4)
{
    // Each thread handles 2 chunks: i0 and i0+256 (both coalesced within warp).
    int i0 = blockIdx.x * (blockDim.x * 2) + threadIdx.x;
    int i1 = i0 + blockDim.x;

    if (i1 < n4) {
        // Front-batch all 8 independent streaming loads (MLP=8)
        float4 b0  = __ldcs(&bounds[i0]);
        float4 sp0 = __ldcs(&slopes_prev[i0]);
        float4 sh0 = __ldcs(&shifts_prev[i0]);
        float4 bp0 = __ldcs(&bounds_prev[i0]);
        float4 b1  = __ldcs(&bounds[i1]);
        float4 sp1 = __ldcs(&slopes_prev[i1]);
        float4 sh1 = __ldcs(&shifts_prev[i1]);
        float4 bp1 = __ldcs(&bounds_prev[i1]);

        float4 o0 = process_chunk(b0, sp0, sh0, bp0);
        float4 o1 = process_chunk(b1, sp1, sh1, bp1);

        __stcs(&out[i0], o0);
        __stcs(&out[i1], o1);
    } else if (i0 < n4) {
        float4 b  = __ldcs(&bounds[i0]);
        float4 sp = __ldcs(&slopes_prev[i0]);
        float4 sh = __ldcs(&shifts_prev[i0]);
        float4 bp = __ldcs(&bounds_prev[i0]);
        __stcs(&out[i0], process_chunk(b, sp, sh, bp));
    }
}

extern "C" void kernel_launch(void* const* d_in, const int* in_sizes, int n_in,
                              void* d_out, int out_size)
{
    const float4* bounds      = (const float4*)d_in[0];
    const float4* slopes_prev = (const float4*)d_in[1];
    const float4* shifts_prev = (const float4*)d_in[2];
    const float4* bounds_prev = (const float4*)d_in[3];
    float4* out = (float4*)d_out;

    int n4 = in_sizes[0] / 4;             // N/2 float4 chunks

    int threads = 256;
    int chunks_per_block = threads * 2;
    int blocks = (n4 + chunks_per_block - 1) / chunks_per_block;
    spu_transformer_kernel<<<blocks, threads>>>(bounds, slopes_prev, shifts_prev,
                                                bounds_prev, out, n4);
}